// round 2
// baseline (speedup 1.0000x reference)
#include <cuda_runtime.h>
#include <math.h>

// Problem constants
#define BB 4
#define SS 2048
#define DD 512
#define HH 8
#define HD 64
#define BH (BB*HH)

// Scratch (device globals — no allocation allowed)
__device__ float g_q[BH * SS * HD];     // [b,h,s,hd]
__device__ float g_k[BH * SS * HD];
__device__ float g_v[BH * SS * HD];
__device__ float g_x[BB * SS * DD];     // [b,s,h*hd] attn output before Wo

// ---------------------------------------------------------------------------
// Projection GEMM: C[m,n] = sum_k X[m,k]*W[n,k] + bias[n]
// M=8192, N=512, K=512. scatter=1 -> write to [b,h,s,hd] layout; else row-major.
// Tiles: BM=BN=64, BK=16, 256 threads, 4x4 per thread.
// ---------------------------------------------------------------------------
__global__ __launch_bounds__(256) void proj_kernel(
    const float* __restrict__ X, const float* __restrict__ W,
    const float* __restrict__ bias, float* __restrict__ out, int scatter)
{
    const int K = DD;
    __shared__ __align__(16) float As[16][68];
    __shared__ __align__(16) float Bs[16][68];

    const int t  = threadIdx.x;
    const int m0 = blockIdx.y * 64;
    const int n0 = blockIdx.x * 64;
    const int lr = t >> 2;           // 0..63
    const int lk = (t & 3) * 4;      // 0,4,8,12
    const int ty = t >> 4;           // 0..15
    const int tx = t & 15;           // 0..15

    float acc[4][4] = {};

    for (int k0 = 0; k0 < K; k0 += 16) {
        float4 av = *(const float4*)&X[(size_t)(m0 + lr) * K + k0 + lk];
        float4 bv = *(const float4*)&W[(size_t)(n0 + lr) * K + k0 + lk];
        As[lk + 0][lr] = av.x; As[lk + 1][lr] = av.y;
        As[lk + 2][lr] = av.z; As[lk + 3][lr] = av.w;
        Bs[lk + 0][lr] = bv.x; Bs[lk + 1][lr] = bv.y;
        Bs[lk + 2][lr] = bv.z; Bs[lk + 3][lr] = bv.w;
        __syncthreads();
        #pragma unroll
        for (int kk = 0; kk < 16; kk++) {
            float4 a = *(float4*)&As[kk][ty * 4];
            float4 b = *(float4*)&Bs[kk][tx * 4];
            acc[0][0] += a.x * b.x; acc[0][1] += a.x * b.y; acc[0][2] += a.x * b.z; acc[0][3] += a.x * b.w;
            acc[1][0] += a.y * b.x; acc[1][1] += a.y * b.y; acc[1][2] += a.y * b.z; acc[1][3] += a.y * b.w;
            acc[2][0] += a.z * b.x; acc[2][1] += a.z * b.y; acc[2][2] += a.z * b.z; acc[2][3] += a.z * b.w;
            acc[3][0] += a.w * b.x; acc[3][1] += a.w * b.y; acc[3][2] += a.w * b.z; acc[3][3] += a.w * b.w;
        }
        __syncthreads();
    }

    #pragma unroll
    for (int i = 0; i < 4; i++) {
        const int m = m0 + ty * 4 + i;
        #pragma unroll
        for (int j = 0; j < 4; j++) {
            const int n = n0 + tx * 4 + j;
            float v = acc[i][j] + bias[n];
            if (scatter) {
                const int b = m >> 11;        // m / S
                const int s = m & (SS - 1);
                const int h = n >> 6;         // n / HD
                const int hd = n & (HD - 1);
                out[(((size_t)(b * HH + h)) * SS + s) * HD + hd] = v;
            } else {
                out[(size_t)m * DD + n] = v;
            }
        }
    }
}

// ---------------------------------------------------------------------------
// Scores: dist[bh, i, j] = (q[bh,i,:] . k[bh,j,:]) / 8, masked -> -1e10
// mask is int32 (harness promotes bool -> int32).
// grid: (S/64 ktiles, S/64 qtiles, BH)
// ---------------------------------------------------------------------------
__global__ __launch_bounds__(256) void scores_kernel(
    const int* __restrict__ mask, float* __restrict__ dist)
{
    __shared__ __align__(16) float As[16][68];
    __shared__ __align__(16) float Bs[16][68];

    const int bh = blockIdx.z;
    const int b  = bh >> 3;
    const float* q = g_q + (size_t)bh * SS * HD;
    const float* k = g_k + (size_t)bh * SS * HD;

    const int t  = threadIdx.x;
    const int m0 = blockIdx.y * 64;   // q rows
    const int n0 = blockIdx.x * 64;   // k rows
    const int lr = t >> 2;
    const int lk = (t & 3) * 4;
    const int ty = t >> 4;
    const int tx = t & 15;

    float acc[4][4] = {};

    for (int k0 = 0; k0 < HD; k0 += 16) {
        float4 av = *(const float4*)&q[(size_t)(m0 + lr) * HD + k0 + lk];
        float4 bv = *(const float4*)&k[(size_t)(n0 + lr) * HD + k0 + lk];
        As[lk + 0][lr] = av.x; As[lk + 1][lr] = av.y;
        As[lk + 2][lr] = av.z; As[lk + 3][lr] = av.w;
        Bs[lk + 0][lr] = bv.x; Bs[lk + 1][lr] = bv.y;
        Bs[lk + 2][lr] = bv.z; Bs[lk + 3][lr] = bv.w;
        __syncthreads();
        #pragma unroll
        for (int kk = 0; kk < 16; kk++) {
            float4 a = *(float4*)&As[kk][ty * 4];
            float4 bfr = *(float4*)&Bs[kk][tx * 4];
            acc[0][0] += a.x * bfr.x; acc[0][1] += a.x * bfr.y; acc[0][2] += a.x * bfr.z; acc[0][3] += a.x * bfr.w;
            acc[1][0] += a.y * bfr.x; acc[1][1] += a.y * bfr.y; acc[1][2] += a.y * bfr.z; acc[1][3] += a.y * bfr.w;
            acc[2][0] += a.z * bfr.x; acc[2][1] += a.z * bfr.y; acc[2][2] += a.z * bfr.z; acc[2][3] += a.z * bfr.w;
            acc[3][0] += a.w * bfr.x; acc[3][1] += a.w * bfr.y; acc[3][2] += a.w * bfr.z; acc[3][3] += a.w * bfr.w;
        }
        __syncthreads();
    }

    const size_t dbase = (size_t)bh * SS * SS;
    const size_t mbase = (size_t)b * SS * SS;
    #pragma unroll
    for (int i = 0; i < 4; i++) {
        const int m = m0 + ty * 4 + i;
        #pragma unroll
        for (int j = 0; j < 4; j++) {
            const int n = n0 + tx * 4 + j;
            float s = acc[i][j] * 0.125f;
            if (mask[mbase + (size_t)m * SS + n] != 0) s = -1e10f;
            dist[dbase + (size_t)m * SS + n] = s;
        }
    }
}

// ---------------------------------------------------------------------------
// In-place row softmax over dist: 65536 rows of 2048, one block per row.
// ---------------------------------------------------------------------------
__global__ __launch_bounds__(256) void softmax_kernel(float* __restrict__ dist)
{
    float* p = dist + (size_t)blockIdx.x * SS;
    const int t = threadIdx.x;
    float4 a = ((float4*)p)[t];
    float4 b = ((float4*)p)[t + 256];

    float mx = fmaxf(fmaxf(fmaxf(a.x, a.y), fmaxf(a.z, a.w)),
                     fmaxf(fmaxf(b.x, b.y), fmaxf(b.z, b.w)));
    __shared__ float red[8];
    #pragma unroll
    for (int o = 16; o > 0; o >>= 1) mx = fmaxf(mx, __shfl_xor_sync(0xffffffffu, mx, o));
    if ((t & 31) == 0) red[t >> 5] = mx;
    __syncthreads();
    mx = red[0];
    #pragma unroll
    for (int w = 1; w < 8; w++) mx = fmaxf(mx, red[w]);
    __syncthreads();

    a.x = __expf(a.x - mx); a.y = __expf(a.y - mx); a.z = __expf(a.z - mx); a.w = __expf(a.w - mx);
    b.x = __expf(b.x - mx); b.y = __expf(b.y - mx); b.z = __expf(b.z - mx); b.w = __expf(b.w - mx);

    float sum = a.x + a.y + a.z + a.w + b.x + b.y + b.z + b.w;
    #pragma unroll
    for (int o = 16; o > 0; o >>= 1) sum += __shfl_xor_sync(0xffffffffu, sum, o);
    if ((t & 31) == 0) red[t >> 5] = sum;
    __syncthreads();
    sum = red[0];
    #pragma unroll
    for (int w = 1; w < 8; w++) sum += red[w];

    const float inv = 1.0f / sum;
    a.x *= inv; a.y *= inv; a.z *= inv; a.w *= inv;
    b.x *= inv; b.y *= inv; b.z *= inv; b.w *= inv;
    ((float4*)p)[t] = a;
    ((float4*)p)[t + 256] = b;
}

// ---------------------------------------------------------------------------
// PV: x[b, m, h*64+n] = sum_k dist[bh,m,k] * v[bh,k,n]   (K=2048, N=64)
// grid: (1, S/64 mtiles, BH)
// ---------------------------------------------------------------------------
__global__ __launch_bounds__(256) void av_kernel(const float* __restrict__ dist)
{
    __shared__ __align__(16) float As[16][68];
    __shared__ __align__(16) float Bs[16][68];

    const int bh = blockIdx.z;
    const int b  = bh >> 3;
    const int h  = bh & 7;
    const float* P = dist + (size_t)bh * SS * SS;
    const float* V = g_v + (size_t)bh * SS * HD;

    const int t  = threadIdx.x;
    const int m0 = blockIdx.y * 64;
    const int lr = t >> 2;
    const int lk = (t & 3) * 4;
    const int kB = t >> 4;          // 0..15 (B-tile k row)
    const int n4 = (t & 15) * 4;    // 0..60
    const int ty = t >> 4;
    const int tx = t & 15;

    float acc[4][4] = {};

    for (int k0 = 0; k0 < SS; k0 += 16) {
        float4 av = *(const float4*)&P[(size_t)(m0 + lr) * SS + k0 + lk];
        As[lk + 0][lr] = av.x; As[lk + 1][lr] = av.y;
        As[lk + 2][lr] = av.z; As[lk + 3][lr] = av.w;
        float4 bv = *(const float4*)&V[(size_t)(k0 + kB) * HD + n4];
        *(float4*)&Bs[kB][n4] = bv;
        __syncthreads();
        #pragma unroll
        for (int kk = 0; kk < 16; kk++) {
            float4 a = *(float4*)&As[kk][ty * 4];
            float4 bfr = *(float4*)&Bs[kk][tx * 4];
            acc[0][0] += a.x * bfr.x; acc[0][1] += a.x * bfr.y; acc[0][2] += a.x * bfr.z; acc[0][3] += a.x * bfr.w;
            acc[1][0] += a.y * bfr.x; acc[1][1] += a.y * bfr.y; acc[1][2] += a.y * bfr.z; acc[1][3] += a.y * bfr.w;
            acc[2][0] += a.z * bfr.x; acc[2][1] += a.z * bfr.y; acc[2][2] += a.z * bfr.z; acc[2][3] += a.z * bfr.w;
            acc[3][0] += a.w * bfr.x; acc[3][1] += a.w * bfr.y; acc[3][2] += a.w * bfr.z; acc[3][3] += a.w * bfr.w;
        }
        __syncthreads();
    }

    #pragma unroll
    for (int i = 0; i < 4; i++) {
        const int m = m0 + ty * 4 + i;
        #pragma unroll
        for (int j = 0; j < 4; j++) {
            const int n = tx * 4 + j;
            g_x[((size_t)(b * SS + m)) * DD + h * HD + n] = acc[i][j];
        }
    }
}

// ---------------------------------------------------------------------------
extern "C" void kernel_launch(void* const* d_in, const int* in_sizes, int n_in,
                              void* d_out, int out_size)
{
    const float* Q  = (const float*)d_in[0];
    const float* K  = (const float*)d_in[1];
    const float* V  = (const float*)d_in[2];
    const int*   mask = (const int*)d_in[3];
    const float* Wq = (const float*)d_in[4];
    const float* bq = (const float*)d_in[5];
    const float* Wk = (const float*)d_in[6];
    const float* bk = (const float*)d_in[7];
    const float* Wv = (const float*)d_in[8];
    const float* bv = (const float*)d_in[9];
    const float* Wo = (const float*)d_in[10];
    const float* bo = (const float*)d_in[11];

    float* out_x    = (float*)d_out;                        // [B,S,D]
    float* out_dist = (float*)d_out + (size_t)BB * SS * DD; // [B,H,S,S]

    void* pq; void* pk; void* pv; void* px;
    cudaGetSymbolAddress(&pq, g_q);
    cudaGetSymbolAddress(&pk, g_k);
    cudaGetSymbolAddress(&pv, g_v);
    cudaGetSymbolAddress(&px, g_x);

    dim3 blk(256);
    dim3 gproj(DD / 64, (BB * SS) / 64);      // (8, 128)
    proj_kernel<<<gproj, blk>>>(Q, Wq, bq, (float*)pq, 1);
    proj_kernel<<<gproj, blk>>>(K, Wk, bk, (float*)pk, 1);
    proj_kernel<<<gproj, blk>>>(V, Wv, bv, (float*)pv, 1);

    dim3 gsc(SS / 64, SS / 64, BH);           // (32, 32, 32)
    scores_kernel<<<gsc, blk>>>(mask, out_dist);

    softmax_kernel<<<BH * SS, blk>>>(out_dist);

    dim3 gav(1, SS / 64, BH);                 // (1, 32, 32)
    av_kernel<<<gav, blk>>>(out_dist);

    proj_kernel<<<gproj, blk>>>((const float*)px, Wo, bo, out_x, 0);
}

// round 3
// speedup vs baseline: 3.0369x; 3.0369x over previous
#include <cuda_runtime.h>
#include <math.h>

// Problem constants
#define BB 4
#define SS 2048
#define DD 512
#define HH 8
#define HD 64
#define BH (BB*HH)

// Scratch (device globals — no allocation allowed)
__device__ float    g_q[BH * SS * HD];      // [b,h,s,hd] fp32
__device__ float    g_k[BH * SS * HD];
__device__ float    g_v[BH * SS * HD];
__device__ float    g_x[BB * SS * DD];      // [b,s,h*hd] attn out before Wo
__device__ float    g_sum[BH * SS];         // softmax row sums (atomic)
__device__ unsigned g_mbits[BB * SS * (SS/32)]; // bit-packed mask

// ---------------------------------------------------------------------------
// helpers
// ---------------------------------------------------------------------------
__device__ __forceinline__ unsigned f2tf(float x) {
    unsigned r;
    asm("cvt.rna.tf32.f32 %0, %1;" : "=r"(r) : "f"(x));
    return r;
}

__device__ __forceinline__ void mma_tf32(float c[4], const unsigned a[4], const unsigned b[2]) {
    asm volatile(
        "mma.sync.aligned.m16n8k8.row.col.f32.tf32.tf32.f32 "
        "{%0,%1,%2,%3},{%4,%5,%6,%7},{%8,%9},{%0,%1,%2,%3};"
        : "+f"(c[0]), "+f"(c[1]), "+f"(c[2]), "+f"(c[3])
        : "r"(a[0]), "r"(a[1]), "r"(a[2]), "r"(a[3]), "r"(b[0]), "r"(b[1]));
}

// ---------------------------------------------------------------------------
// pack mask (int32 0/1) into bits: one word covers 32 consecutive n
// ---------------------------------------------------------------------------
__global__ __launch_bounds__(256) void pack_mask_kernel(
    const int* __restrict__ mask, unsigned* __restrict__ bits)
{
    int w = blockIdx.x * 256 + threadIdx.x;           // 0 .. B*S*64-1
    const int4* p = (const int4*)(mask + (size_t)w * 32);
    unsigned v = 0;
    #pragma unroll
    for (int i = 0; i < 8; i++) {
        int4 q = p[i];
        v |= (unsigned)(q.x != 0) << (i * 4 + 0);
        v |= (unsigned)(q.y != 0) << (i * 4 + 1);
        v |= (unsigned)(q.z != 0) << (i * 4 + 2);
        v |= (unsigned)(q.w != 0) << (i * 4 + 3);
    }
    bits[w] = v;
}

__global__ __launch_bounds__(256) void zero_sums_kernel(float* __restrict__ s)
{
    s[blockIdx.x * 256 + threadIdx.x] = 0.0f;
}

// ---------------------------------------------------------------------------
// Projection GEMM (tf32 MMA): C[m,n] = sum_k X[m,k]*W[n,k] + bias[n]
// M=8192, N=512, K=512. Block 128x128, 8 warps (2m x 4n), warp 64x32.
// scatter=1 -> out in [b,h,s,hd]; else row-major [m][512].
// ---------------------------------------------------------------------------
__global__ __launch_bounds__(256) void proj_mma(
    const float* __restrict__ X, const float* __restrict__ W,
    const float* __restrict__ bias, float* __restrict__ out, int scatter)
{
    __shared__ __align__(16) unsigned As[128 * 36];
    __shared__ __align__(16) unsigned Bs[128 * 36];

    const int t = threadIdx.x;
    const int warp = t >> 5, lane = t & 31;
    const int wm = warp >> 2, wn = warp & 3;      // 2 x 4
    const int g = lane >> 2, tig = lane & 3;
    const int m0 = blockIdx.y * 128, n0 = blockIdx.x * 128;

    float acc[4][4][4] = {};                      // [mtile][ntile][c]

    for (int k0 = 0; k0 < DD; k0 += 32) {
        #pragma unroll
        for (int i = 0; i < 4; i++) {
            int f = i * 256 + t;                  // 0..1023
            int r = f >> 3, c4 = (f & 7) * 4;
            float4 xv = *(const float4*)&X[(size_t)(m0 + r) * DD + k0 + c4];
            *(uint4*)&As[r * 36 + c4] = make_uint4(f2tf(xv.x), f2tf(xv.y), f2tf(xv.z), f2tf(xv.w));
            float4 wv = *(const float4*)&W[(size_t)(n0 + r) * DD + k0 + c4];
            *(uint4*)&Bs[r * 36 + c4] = make_uint4(f2tf(wv.x), f2tf(wv.y), f2tf(wv.z), f2tf(wv.w));
        }
        __syncthreads();

        #pragma unroll
        for (int kk = 0; kk < 32; kk += 8) {
            unsigned af[4][4], bf[4][2];
            #pragma unroll
            for (int mt = 0; mt < 4; mt++) {
                int mrow = wm * 64 + mt * 16;
                af[mt][0] = As[(mrow + g) * 36 + kk + tig];
                af[mt][1] = As[(mrow + g + 8) * 36 + kk + tig];
                af[mt][2] = As[(mrow + g) * 36 + kk + tig + 4];
                af[mt][3] = As[(mrow + g + 8) * 36 + kk + tig + 4];
            }
            #pragma unroll
            for (int nt = 0; nt < 4; nt++) {
                int ncol = wn * 32 + nt * 8 + g;
                bf[nt][0] = Bs[ncol * 36 + kk + tig];
                bf[nt][1] = Bs[ncol * 36 + kk + tig + 4];
            }
            #pragma unroll
            for (int mt = 0; mt < 4; mt++)
                #pragma unroll
                for (int nt = 0; nt < 4; nt++)
                    mma_tf32(acc[mt][nt], af[mt], bf[nt]);
        }
        __syncthreads();
    }

    #pragma unroll
    for (int nt = 0; nt < 4; nt++) {
        const int col = n0 + wn * 32 + nt * 8 + 2 * tig;
        const float b0v = bias[col], b1v = bias[col + 1];
        #pragma unroll
        for (int mt = 0; mt < 4; mt++) {
            #pragma unroll
            for (int half = 0; half < 2; half++) {
                int m = m0 + wm * 64 + mt * 16 + g + half * 8;
                float2 v;
                v.x = acc[mt][nt][half * 2 + 0] + b0v;
                v.y = acc[mt][nt][half * 2 + 1] + b1v;
                if (scatter) {
                    int b = m >> 11, s = m & (SS - 1);
                    int h = col >> 6, hd = col & (HD - 1);
                    *(float2*)&out[(((size_t)(b * HH + h)) * SS + s) * HD + hd] = v;
                } else {
                    *(float2*)&out[(size_t)m * DD + col] = v;
                }
            }
        }
    }
}

// ---------------------------------------------------------------------------
// Scores (tf32 MMA) + fused exp/mask + atomic row sums.
// dist[bh,m,n] = exp((q.k)/8) (0 if masked), UNNORMALIZED.
// Block 128x128, K=64 single phase. grid (16 n, 16 m, 32 bh).
// ---------------------------------------------------------------------------
__global__ __launch_bounds__(256) void scores_mma(
    float* __restrict__ dist)
{
    extern __shared__ __align__(16) unsigned sh[];
    unsigned* As = sh;                 // [128][68]  q tile (m,k)
    unsigned* Bs = sh + 128 * 68;      // [128][68]  k tile (n,k)

    const int t = threadIdx.x;
    const int warp = t >> 5, lane = t & 31;
    const int wm = warp >> 2, wn = warp & 3;      // 2 x 4
    const int g = lane >> 2, tig = lane & 3;
    const int bh = blockIdx.z;
    const int b = bh >> 3;
    const int m0 = blockIdx.y * 128, n0 = blockIdx.x * 128;

    const float* q = g_q + (size_t)bh * SS * HD;
    const float* k = g_k + (size_t)bh * SS * HD;

    #pragma unroll
    for (int i = 0; i < 8; i++) {
        int f = i * 256 + t;                      // 0..2047
        int r = f >> 4, c4 = (f & 15) * 4;
        float4 qv = *(const float4*)&q[(size_t)(m0 + r) * HD + c4];
        *(uint4*)&As[r * 68 + c4] = make_uint4(f2tf(qv.x), f2tf(qv.y), f2tf(qv.z), f2tf(qv.w));
        float4 kv = *(const float4*)&k[(size_t)(n0 + r) * HD + c4];
        *(uint4*)&Bs[r * 68 + c4] = make_uint4(f2tf(kv.x), f2tf(kv.y), f2tf(kv.z), f2tf(kv.w));
    }
    __syncthreads();

    float acc[4][4][4] = {};
    #pragma unroll
    for (int kk = 0; kk < 64; kk += 8) {
        unsigned af[4][4], bf[4][2];
        #pragma unroll
        for (int mt = 0; mt < 4; mt++) {
            int mrow = wm * 64 + mt * 16;
            af[mt][0] = As[(mrow + g) * 68 + kk + tig];
            af[mt][1] = As[(mrow + g + 8) * 68 + kk + tig];
            af[mt][2] = As[(mrow + g) * 68 + kk + tig + 4];
            af[mt][3] = As[(mrow + g + 8) * 68 + kk + tig + 4];
        }
        #pragma unroll
        for (int nt = 0; nt < 4; nt++) {
            int ncol = wn * 32 + nt * 8 + g;
            bf[nt][0] = Bs[ncol * 68 + kk + tig];
            bf[nt][1] = Bs[ncol * 68 + kk + tig + 4];
        }
        #pragma unroll
        for (int mt = 0; mt < 4; mt++)
            #pragma unroll
            for (int nt = 0; nt < 4; nt++)
                mma_tf32(acc[mt][nt], af[mt], bf[nt]);
    }

    // epilogue: scale, mask, exp, row sums, store unnormalized exp
    const size_t dbase = (size_t)bh * SS * SS;
    const int wq = blockIdx.x * 4 + wn;           // mask word column
    #pragma unroll
    for (int mt = 0; mt < 4; mt++) {
        #pragma unroll
        for (int half = 0; half < 2; half++) {
            int row = m0 + wm * 64 + mt * 16 + g + half * 8;
            unsigned mb = g_mbits[((size_t)b * SS + row) * (SS/32) + wq];
            float rsum = 0.0f;
            #pragma unroll
            for (int nt = 0; nt < 4; nt++) {
                int nloc = nt * 8 + 2 * tig;
                float v0 = acc[mt][nt][half * 2 + 0] * 0.125f;
                float v1 = acc[mt][nt][half * 2 + 1] * 0.125f;
                float e0 = ((mb >> nloc) & 1u) ? 0.0f : __expf(v0);
                float e1 = ((mb >> (nloc + 1)) & 1u) ? 0.0f : __expf(v1);
                rsum += e0 + e1;
                float2 ev; ev.x = e0; ev.y = e1;
                *(float2*)&dist[dbase + (size_t)row * SS + n0 + wn * 32 + nloc] = ev;
            }
            rsum += __shfl_xor_sync(0xffffffffu, rsum, 1);
            rsum += __shfl_xor_sync(0xffffffffu, rsum, 2);
            if (tig == 0) atomicAdd(&g_sum[bh * SS + row], rsum);
        }
    }
}

// ---------------------------------------------------------------------------
// AV (tf32 MMA): x = P_norm @ V; normalizes dist in place while loading.
// Block 128m x 64n, 8 warps (4m x 2n), warp 32x32. grid (16 m, 32 bh).
// ---------------------------------------------------------------------------
__global__ __launch_bounds__(256) void av_mma(float* __restrict__ dist)
{
    __shared__ __align__(16) unsigned As[128 * 36];   // P tile (m,k)
    __shared__ __align__(16) unsigned Bs[32 * 72];    // V tile (k,n)
    __shared__ float inv_s[128];

    const int t = threadIdx.x;
    const int warp = t >> 5, lane = t & 31;
    const int wm = warp >> 1, wn = warp & 1;      // 4 x 2
    const int g = lane >> 2, tig = lane & 3;
    const int bh = blockIdx.y;
    const int b = bh >> 3, h = bh & 7;
    const int m0 = blockIdx.x * 128;

    float* P = dist + (size_t)bh * SS * SS;
    const float* V = g_v + (size_t)bh * SS * HD;

    if (t < 128) {
        float s = g_sum[bh * SS + m0 + t];
        inv_s[t] = 1.0f / s;
    }
    __syncthreads();

    float acc[2][4][4] = {};

    for (int k0 = 0; k0 < SS; k0 += 32) {
        #pragma unroll
        for (int i = 0; i < 4; i++) {
            int f = i * 256 + t;
            int r = f >> 3, c4 = (f & 7) * 4;
            float4 pv = *(const float4*)&P[(size_t)(m0 + r) * SS + k0 + c4];
            float is = inv_s[r];
            pv.x *= is; pv.y *= is; pv.z *= is; pv.w *= is;
            *(float4*)&P[(size_t)(m0 + r) * SS + k0 + c4] = pv;   // write normalized back
            *(uint4*)&As[r * 36 + c4] = make_uint4(f2tf(pv.x), f2tf(pv.y), f2tf(pv.z), f2tf(pv.w));
        }
        #pragma unroll
        for (int i = 0; i < 2; i++) {
            int f = i * 256 + t;
            int r = f >> 4, c4 = (f & 15) * 4;
            float4 vv = *(const float4*)&V[(size_t)(k0 + r) * HD + c4];
            *(uint4*)&Bs[r * 72 + c4] = make_uint4(f2tf(vv.x), f2tf(vv.y), f2tf(vv.z), f2tf(vv.w));
        }
        __syncthreads();

        #pragma unroll
        for (int kk = 0; kk < 32; kk += 8) {
            unsigned af[2][4], bf[4][2];
            #pragma unroll
            for (int mt = 0; mt < 2; mt++) {
                int mrow = wm * 32 + mt * 16;
                af[mt][0] = As[(mrow + g) * 36 + kk + tig];
                af[mt][1] = As[(mrow + g + 8) * 36 + kk + tig];
                af[mt][2] = As[(mrow + g) * 36 + kk + tig + 4];
                af[mt][3] = As[(mrow + g + 8) * 36 + kk + tig + 4];
            }
            #pragma unroll
            for (int nt = 0; nt < 4; nt++) {
                int ncol = wn * 32 + nt * 8 + g;
                bf[nt][0] = Bs[(kk + tig) * 72 + ncol];
                bf[nt][1] = Bs[(kk + tig + 4) * 72 + ncol];
            }
            #pragma unroll
            for (int mt = 0; mt < 2; mt++)
                #pragma unroll
                for (int nt = 0; nt < 4; nt++)
                    mma_tf32(acc[mt][nt], af[mt], bf[nt]);
        }
        __syncthreads();
    }

    #pragma unroll
    for (int mt = 0; mt < 2; mt++) {
        #pragma unroll
        for (int nt = 0; nt < 4; nt++) {
            #pragma unroll
            for (int half = 0; half < 2; half++) {
                int row = m0 + wm * 32 + mt * 16 + g + half * 8;
                int col = wn * 32 + nt * 8 + 2 * tig;
                float2 v;
                v.x = acc[mt][nt][half * 2 + 0];
                v.y = acc[mt][nt][half * 2 + 1];
                *(float2*)&g_x[((size_t)(b * SS + row)) * DD + h * HD + col] = v;
            }
        }
    }
}

// ---------------------------------------------------------------------------
extern "C" void kernel_launch(void* const* d_in, const int* in_sizes, int n_in,
                              void* d_out, int out_size)
{
    const float* Q  = (const float*)d_in[0];
    const float* K  = (const float*)d_in[1];
    const float* V  = (const float*)d_in[2];
    const int*   mask = (const int*)d_in[3];
    const float* Wq = (const float*)d_in[4];
    const float* bq = (const float*)d_in[5];
    const float* Wk = (const float*)d_in[6];
    const float* bk = (const float*)d_in[7];
    const float* Wv = (const float*)d_in[8];
    const float* bv = (const float*)d_in[9];
    const float* Wo = (const float*)d_in[10];
    const float* bo = (const float*)d_in[11];

    float* out_x    = (float*)d_out;                        // [B,S,D]
    float* out_dist = (float*)d_out + (size_t)BB * SS * DD; // [B,H,S,S]

    void* pq; void* pk; void* pv; void* px; void* psum; void* pbits;
    cudaGetSymbolAddress(&pq, g_q);
    cudaGetSymbolAddress(&pk, g_k);
    cudaGetSymbolAddress(&pv, g_v);
    cudaGetSymbolAddress(&px, g_x);
    cudaGetSymbolAddress(&psum, g_sum);
    cudaGetSymbolAddress(&pbits, g_mbits);

    cudaFuncSetAttribute(scores_mma, cudaFuncAttributeMaxDynamicSharedMemorySize, 2 * 128 * 68 * 4);

    dim3 blk(256);

    zero_sums_kernel<<<(BH * SS) / 256, blk>>>((float*)psum);
    pack_mask_kernel<<<(BB * SS * (SS/32)) / 256, blk>>>(mask, (unsigned*)pbits);

    dim3 gproj(DD / 128, (BB * SS) / 128);                  // (4, 64)
    proj_mma<<<gproj, blk>>>(Q, Wq, bq, (float*)pq, 1);
    proj_mma<<<gproj, blk>>>(K, Wk, bk, (float*)pk, 1);
    proj_mma<<<gproj, blk>>>(V, Wv, bv, (float*)pv, 1);

    dim3 gsc(SS / 128, SS / 128, BH);                       // (16, 16, 32)
    scores_mma<<<gsc, blk, 2 * 128 * 68 * 4>>>(out_dist);

    dim3 gav(SS / 128, BH);                                 // (16, 32)
    av_mma<<<gav, blk>>>(out_dist);

    proj_mma<<<gproj, blk>>>((const float*)px, Wo, bo, out_x, 0);
}

// round 4
// speedup vs baseline: 3.1947x; 1.0520x over previous
#include <cuda_runtime.h>
#include <math.h>

// Problem constants
#define BB 4
#define SS 2048
#define DD 512
#define HH 8
#define HD 64
#define BH (BB*HH)

// Scratch (device globals — no allocation allowed)
__device__ float    g_q[BH * SS * HD];      // [b,h,s,hd] fp32
__device__ float    g_k[BH * SS * HD];
__device__ float    g_v[BH * SS * HD];
__device__ float    g_x[BB * SS * DD];      // [b,s,h*hd] attn out before Wo
__device__ unsigned g_mbits[BB * SS * (SS/32)]; // bit-packed mask

// ---------------------------------------------------------------------------
__device__ __forceinline__ unsigned f2tf(float x) {
    unsigned r;
    asm("cvt.rna.tf32.f32 %0, %1;" : "=r"(r) : "f"(x));
    return r;
}

__device__ __forceinline__ void mma_tf32(float c[4], const unsigned a[4], const unsigned b[2]) {
    asm volatile(
        "mma.sync.aligned.m16n8k8.row.col.f32.tf32.tf32.f32 "
        "{%0,%1,%2,%3},{%4,%5,%6,%7},{%8,%9},{%0,%1,%2,%3};"
        : "+f"(c[0]), "+f"(c[1]), "+f"(c[2]), "+f"(c[3])
        : "r"(a[0]), "r"(a[1]), "r"(a[2]), "r"(a[3]), "r"(b[0]), "r"(b[1]));
}

// ---------------------------------------------------------------------------
__global__ __launch_bounds__(256) void pack_mask_kernel(
    const int* __restrict__ mask, unsigned* __restrict__ bits)
{
    int w = blockIdx.x * 256 + threadIdx.x;
    const int4* p = (const int4*)(mask + (size_t)w * 32);
    unsigned v = 0;
    #pragma unroll
    for (int i = 0; i < 8; i++) {
        int4 q = p[i];
        v |= (unsigned)(q.x != 0) << (i * 4 + 0);
        v |= (unsigned)(q.y != 0) << (i * 4 + 1);
        v |= (unsigned)(q.z != 0) << (i * 4 + 2);
        v |= (unsigned)(q.w != 0) << (i * 4 + 3);
    }
    bits[w] = v;
}

// ---------------------------------------------------------------------------
// Projection GEMM (tf32 MMA): C = X @ W^T + bias. Block 128x128, 8 warps.
// ---------------------------------------------------------------------------
__global__ __launch_bounds__(256) void proj_mma(
    const float* __restrict__ X, const float* __restrict__ W,
    const float* __restrict__ bias, float* __restrict__ out, int scatter)
{
    __shared__ __align__(16) unsigned As[128 * 36];
    __shared__ __align__(16) unsigned Bs[128 * 36];

    const int t = threadIdx.x;
    const int warp = t >> 5, lane = t & 31;
    const int wm = warp >> 2, wn = warp & 3;
    const int g = lane >> 2, tig = lane & 3;
    const int m0 = blockIdx.y * 128, n0 = blockIdx.x * 128;

    float acc[4][4][4] = {};

    for (int k0 = 0; k0 < DD; k0 += 32) {
        #pragma unroll
        for (int i = 0; i < 4; i++) {
            int f = i * 256 + t;
            int r = f >> 3, c4 = (f & 7) * 4;
            float4 xv = *(const float4*)&X[(size_t)(m0 + r) * DD + k0 + c4];
            *(uint4*)&As[r * 36 + c4] = make_uint4(f2tf(xv.x), f2tf(xv.y), f2tf(xv.z), f2tf(xv.w));
            float4 wv = *(const float4*)&W[(size_t)(n0 + r) * DD + k0 + c4];
            *(uint4*)&Bs[r * 36 + c4] = make_uint4(f2tf(wv.x), f2tf(wv.y), f2tf(wv.z), f2tf(wv.w));
        }
        __syncthreads();

        #pragma unroll
        for (int kk = 0; kk < 32; kk += 8) {
            unsigned af[4][4], bf[4][2];
            #pragma unroll
            for (int mt = 0; mt < 4; mt++) {
                int mrow = wm * 64 + mt * 16;
                af[mt][0] = As[(mrow + g) * 36 + kk + tig];
                af[mt][1] = As[(mrow + g + 8) * 36 + kk + tig];
                af[mt][2] = As[(mrow + g) * 36 + kk + tig + 4];
                af[mt][3] = As[(mrow + g + 8) * 36 + kk + tig + 4];
            }
            #pragma unroll
            for (int nt = 0; nt < 4; nt++) {
                int ncol = wn * 32 + nt * 8 + g;
                bf[nt][0] = Bs[ncol * 36 + kk + tig];
                bf[nt][1] = Bs[ncol * 36 + kk + tig + 4];
            }
            #pragma unroll
            for (int mt = 0; mt < 4; mt++)
                #pragma unroll
                for (int nt = 0; nt < 4; nt++)
                    mma_tf32(acc[mt][nt], af[mt], bf[nt]);
        }
        __syncthreads();
    }

    #pragma unroll
    for (int nt = 0; nt < 4; nt++) {
        const int col = n0 + wn * 32 + nt * 8 + 2 * tig;
        const float b0v = bias[col], b1v = bias[col + 1];
        #pragma unroll
        for (int mt = 0; mt < 4; mt++) {
            #pragma unroll
            for (int half = 0; half < 2; half++) {
                int m = m0 + wm * 64 + mt * 16 + g + half * 8;
                float2 v;
                v.x = acc[mt][nt][half * 2 + 0] + b0v;
                v.y = acc[mt][nt][half * 2 + 1] + b1v;
                if (scatter) {
                    int b = m >> 11, s = m & (SS - 1);
                    int h = col >> 6, hd = col & (HD - 1);
                    *(float2*)&out[(((size_t)(b * HH + h)) * SS + s) * HD + hd] = v;
                } else {
                    *(float2*)&out[(size_t)m * DD + col] = v;
                }
            }
        }
    }
}

// ---------------------------------------------------------------------------
// Fused attention: block owns (bh, 128 q-rows).
// Phase A: row sums of exp(masked scores) via tf32 MMA recompute-free pass.
// Phase B: recompute scores, normalize, write final dist ONCE, and do PV MMA.
// grid (SS/128, BH), 256 threads, ~174KB dynamic smem.
// ---------------------------------------------------------------------------
__global__ __launch_bounds__(256) void attn_fused(float* __restrict__ dist)
{
    extern __shared__ __align__(16) unsigned sh[];
    unsigned* Qs = sh;              // [128][68]  q (m,k)
    unsigned* Ks = sh + 8704;       // [128][68]  k (n,k)
    unsigned* Ps = sh + 17408;      // [128][132] p (m,k2) for PV
    unsigned* Vs = sh + 34304;      // [128][72]  v (k2,n) k-major
    float* rowsum = (float*)(sh + 43520);  // [128]

    const int t = threadIdx.x;
    const int warp = t >> 5, lane = t & 31;
    const int wm = warp >> 2, wn = warp & 3;   // 2 x 4
    const int g = lane >> 2, tig = lane & 3;
    const int bh = blockIdx.y, b = bh >> 3, h = bh & 7;
    const int m0 = blockIdx.x * 128;

    const float* q = g_q + (size_t)bh * SS * HD;
    const float* k = g_k + (size_t)bh * SS * HD;
    const float* v = g_v + (size_t)bh * SS * HD;

    // load Q tile (stays resident)
    #pragma unroll
    for (int i = 0; i < 8; i++) {
        int f = i * 256 + t;
        int r = f >> 4, c4 = (f & 15) * 4;
        float4 qv = *(const float4*)&q[(size_t)(m0 + r) * HD + c4];
        *(uint4*)&Qs[r * 68 + c4] = make_uint4(f2tf(qv.x), f2tf(qv.y), f2tf(qv.z), f2tf(qv.w));
    }
    if (t < 128) rowsum[t] = 0.0f;

    float rs[4][2] = {};

    // ======== Phase A: row sums ========
    for (int n0 = 0; n0 < SS; n0 += 128) {
        __syncthreads();   // previous iteration's frag reads done (and Q/rowsum init)
        #pragma unroll
        for (int i = 0; i < 8; i++) {
            int f = i * 256 + t;
            int r = f >> 4, c4 = (f & 15) * 4;
            float4 kv = *(const float4*)&k[(size_t)(n0 + r) * HD + c4];
            *(uint4*)&Ks[r * 68 + c4] = make_uint4(f2tf(kv.x), f2tf(kv.y), f2tf(kv.z), f2tf(kv.w));
        }
        __syncthreads();

        float acc[4][4][4] = {};
        #pragma unroll
        for (int kk = 0; kk < 64; kk += 8) {
            unsigned af[4][4], bf[4][2];
            #pragma unroll
            for (int mt = 0; mt < 4; mt++) {
                int mrow = wm * 64 + mt * 16;
                af[mt][0] = Qs[(mrow + g) * 68 + kk + tig];
                af[mt][1] = Qs[(mrow + g + 8) * 68 + kk + tig];
                af[mt][2] = Qs[(mrow + g) * 68 + kk + tig + 4];
                af[mt][3] = Qs[(mrow + g + 8) * 68 + kk + tig + 4];
            }
            #pragma unroll
            for (int nt = 0; nt < 4; nt++) {
                int ncol = wn * 32 + nt * 8 + g;
                bf[nt][0] = Ks[ncol * 68 + kk + tig];
                bf[nt][1] = Ks[ncol * 68 + kk + tig + 4];
            }
            #pragma unroll
            for (int mt = 0; mt < 4; mt++)
                #pragma unroll
                for (int nt = 0; nt < 4; nt++)
                    mma_tf32(acc[mt][nt], af[mt], bf[nt]);
        }

        #pragma unroll
        for (int mt = 0; mt < 4; mt++) {
            #pragma unroll
            for (int half = 0; half < 2; half++) {
                int row = m0 + wm * 64 + mt * 16 + g + half * 8;
                unsigned mb = g_mbits[((size_t)b * SS + row) * (SS/32) + (n0 >> 5) + wn];
                #pragma unroll
                for (int nt = 0; nt < 4; nt++) {
                    int nloc = nt * 8 + 2 * tig;
                    float e0 = ((mb >> nloc) & 1u) ? 0.0f : __expf(acc[mt][nt][half*2+0] * 0.125f);
                    float e1 = ((mb >> (nloc+1)) & 1u) ? 0.0f : __expf(acc[mt][nt][half*2+1] * 0.125f);
                    rs[mt][half] += e0 + e1;
                }
            }
        }
    }

    // reduce row sums (quad shuffle, then shared atomics across the 4 n-warps)
    #pragma unroll
    for (int mt = 0; mt < 4; mt++)
        #pragma unroll
        for (int half = 0; half < 2; half++) {
            float s = rs[mt][half];
            s += __shfl_xor_sync(0xffffffffu, s, 1);
            s += __shfl_xor_sync(0xffffffffu, s, 2);
            if (tig == 0)
                atomicAdd(&rowsum[wm * 64 + mt * 16 + g + half * 8], s);
        }
    __syncthreads();
    if (t < 128) rowsum[t] = 1.0f / rowsum[t];

    // ======== Phase B: recompute, write normalized dist, PV MMA ========
    float y[4][2][4] = {};
    const size_t dbase = (size_t)bh * SS * SS;

    for (int n0 = 0; n0 < SS; n0 += 128) {
        __syncthreads();
        #pragma unroll
        for (int i = 0; i < 8; i++) {
            int f = i * 256 + t;
            int r = f >> 4, c4 = (f & 15) * 4;
            float4 kv = *(const float4*)&k[(size_t)(n0 + r) * HD + c4];
            *(uint4*)&Ks[r * 68 + c4] = make_uint4(f2tf(kv.x), f2tf(kv.y), f2tf(kv.z), f2tf(kv.w));
            float4 vv = *(const float4*)&v[(size_t)(n0 + r) * HD + c4];
            *(uint4*)&Vs[r * 72 + c4] = make_uint4(f2tf(vv.x), f2tf(vv.y), f2tf(vv.z), f2tf(vv.w));
        }
        __syncthreads();

        float acc[4][4][4] = {};
        #pragma unroll
        for (int kk = 0; kk < 64; kk += 8) {
            unsigned af[4][4], bf[4][2];
            #pragma unroll
            for (int mt = 0; mt < 4; mt++) {
                int mrow = wm * 64 + mt * 16;
                af[mt][0] = Qs[(mrow + g) * 68 + kk + tig];
                af[mt][1] = Qs[(mrow + g + 8) * 68 + kk + tig];
                af[mt][2] = Qs[(mrow + g) * 68 + kk + tig + 4];
                af[mt][3] = Qs[(mrow + g + 8) * 68 + kk + tig + 4];
            }
            #pragma unroll
            for (int nt = 0; nt < 4; nt++) {
                int ncol = wn * 32 + nt * 8 + g;
                bf[nt][0] = Ks[ncol * 68 + kk + tig];
                bf[nt][1] = Ks[ncol * 68 + kk + tig + 4];
            }
            #pragma unroll
            for (int mt = 0; mt < 4; mt++)
                #pragma unroll
                for (int nt = 0; nt < 4; nt++)
                    mma_tf32(acc[mt][nt], af[mt], bf[nt]);
        }

        // normalize, write final dist, deposit tf32 P into smem
        #pragma unroll
        for (int mt = 0; mt < 4; mt++) {
            #pragma unroll
            for (int half = 0; half < 2; half++) {
                int rowl = wm * 64 + mt * 16 + g + half * 8;
                int row = m0 + rowl;
                unsigned mb = g_mbits[((size_t)b * SS + row) * (SS/32) + (n0 >> 5) + wn];
                float inv = rowsum[rowl];
                #pragma unroll
                for (int nt = 0; nt < 4; nt++) {
                    int nloc = nt * 8 + 2 * tig;
                    float e0 = ((mb >> nloc) & 1u) ? 0.0f : __expf(acc[mt][nt][half*2+0] * 0.125f) * inv;
                    float e1 = ((mb >> (nloc+1)) & 1u) ? 0.0f : __expf(acc[mt][nt][half*2+1] * 0.125f) * inv;
                    float2 ev; ev.x = e0; ev.y = e1;
                    *(float2*)&dist[dbase + (size_t)row * SS + n0 + wn * 32 + nloc] = ev;
                    uint2 pv; pv.x = f2tf(e0); pv.y = f2tf(e1);
                    *(uint2*)&Ps[rowl * 132 + wn * 32 + nloc] = pv;
                }
            }
        }
        __syncthreads();

        // PV: y += P[128x128] @ V[128x64]; warp covers m 64 (wm), n 16 (wn)
        #pragma unroll
        for (int kk = 0; kk < 128; kk += 8) {
            unsigned af[4][4], bf[2][2];
            #pragma unroll
            for (int mt = 0; mt < 4; mt++) {
                int mrow = wm * 64 + mt * 16;
                af[mt][0] = Ps[(mrow + g) * 132 + kk + tig];
                af[mt][1] = Ps[(mrow + g + 8) * 132 + kk + tig];
                af[mt][2] = Ps[(mrow + g) * 132 + kk + tig + 4];
                af[mt][3] = Ps[(mrow + g + 8) * 132 + kk + tig + 4];
            }
            #pragma unroll
            for (int nt = 0; nt < 2; nt++) {
                int ncol = wn * 16 + nt * 8 + g;
                bf[nt][0] = Vs[(kk + tig) * 72 + ncol];
                bf[nt][1] = Vs[(kk + tig + 4) * 72 + ncol];
            }
            #pragma unroll
            for (int mt = 0; mt < 4; mt++)
                #pragma unroll
                for (int nt = 0; nt < 2; nt++)
                    mma_tf32(y[mt][nt], af[mt], bf[nt]);
        }
    }

    // write attention output
    #pragma unroll
    for (int mt = 0; mt < 4; mt++) {
        #pragma unroll
        for (int nt = 0; nt < 2; nt++) {
            #pragma unroll
            for (int half = 0; half < 2; half++) {
                int row = m0 + wm * 64 + mt * 16 + g + half * 8;
                int col = wn * 16 + nt * 8 + 2 * tig;
                float2 o;
                o.x = y[mt][nt][half * 2 + 0];
                o.y = y[mt][nt][half * 2 + 1];
                *(float2*)&g_x[((size_t)(b * SS + row)) * DD + h * HD + col] = o;
            }
        }
    }
}

// ---------------------------------------------------------------------------
extern "C" void kernel_launch(void* const* d_in, const int* in_sizes, int n_in,
                              void* d_out, int out_size)
{
    const float* Q  = (const float*)d_in[0];
    const float* K  = (const float*)d_in[1];
    const float* V  = (const float*)d_in[2];
    const int*   mask = (const int*)d_in[3];
    const float* Wq = (const float*)d_in[4];
    const float* bq = (const float*)d_in[5];
    const float* Wk = (const float*)d_in[6];
    const float* bk = (const float*)d_in[7];
    const float* Wv = (const float*)d_in[8];
    const float* bv = (const float*)d_in[9];
    const float* Wo = (const float*)d_in[10];
    const float* bo = (const float*)d_in[11];

    float* out_x    = (float*)d_out;                        // [B,S,D]
    float* out_dist = (float*)d_out + (size_t)BB * SS * DD; // [B,H,S,S]

    void* pq; void* pk; void* pv; void* px; void* pbits;
    cudaGetSymbolAddress(&pq, g_q);
    cudaGetSymbolAddress(&pk, g_k);
    cudaGetSymbolAddress(&pv, g_v);
    cudaGetSymbolAddress(&px, g_x);
    cudaGetSymbolAddress(&pbits, g_mbits);

    const int ATTN_SMEM = (43520 + 128) * 4;   // ~174.6 KB
    cudaFuncSetAttribute(attn_fused, cudaFuncAttributeMaxDynamicSharedMemorySize, ATTN_SMEM);

    dim3 blk(256);

    pack_mask_kernel<<<(BB * SS * (SS/32)) / 256, blk>>>(mask, (unsigned*)pbits);

    dim3 gproj(DD / 128, (BB * SS) / 128);                  // (4, 64)
    proj_mma<<<gproj, blk>>>(Q, Wq, bq, (float*)pq, 1);
    proj_mma<<<gproj, blk>>>(K, Wk, bk, (float*)pk, 1);
    proj_mma<<<gproj, blk>>>(V, Wv, bv, (float*)pv, 1);

    dim3 gattn(SS / 128, BH);                               // (16, 32)
    attn_fused<<<gattn, blk, ATTN_SMEM>>>(out_dist);

    proj_mma<<<gproj, blk>>>((const float*)px, Wo, bo, out_x, 0);
}